// round 15
// baseline (speedup 1.0000x reference)
#include <cuda_runtime.h>
#include <cstdint>

// Problem constants (match reference)
#define NUM_CENTERS 1000
#define CAPACITY    512
#define FEAT_DIM    256
#define BATCH       65536

#define VEC_PER_ROW     (FEAT_DIM / 4)       // 64 float4 per row (1 KB)
#define CHUNKS_PER_ROW  (FEAT_DIM / 8)       // 32 x 32B chunks per row
#define SAMPLES_PER_BLK 32
#define THREADS         256
#define TOTAL_CHUNKS    (SAMPLES_PER_BLK * CHUNKS_PER_ROW)  // 1024
#define CHUNKS_PER_THR  (TOTAL_CHUNKS / THREADS)            // 4

// R4-structure kernel with ONE change: 256-bit streaming stores.
// Loads: plain __ldg float4 (proven optimal; v8 loads regressed due to
// within-LDG L1tex wavefront replays). Stores: st.global.cs.v8.b32 -
// stores have no result/replay path, so halving the store-request count
// (4.2M -> 2.1M) can only reduce LTS write-path pressure, which is the
// binding stream (64MiB/replay at ~4 TB/s).
// Each thread owns 4 x 32B chunks; chunk c = k*256+tid; warp covers a
// contiguous 1KB row slice per k -> coalescing identical to R4.

__device__ __forceinline__ void st_cs_256(void* p, float4 a, float4 b) {
    asm volatile("st.global.cs.v8.b32 [%0], {%1,%2,%3,%4,%5,%6,%7,%8};"
                 :: "l"(p),
                    "r"(__float_as_uint(a.x)), "r"(__float_as_uint(a.y)),
                    "r"(__float_as_uint(a.z)), "r"(__float_as_uint(a.w)),
                    "r"(__float_as_uint(b.x)), "r"(__float_as_uint(b.y)),
                    "r"(__float_as_uint(b.z)), "r"(__float_as_uint(b.w))
                 : "memory");
}

__global__ __launch_bounds__(THREADS)
void noise_bank_gather(const int* __restrict__ tgt,
                       const int* __restrict__ ridx,
                       const int* __restrict__ counts,
                       const float4* __restrict__ bank,
                       const float4* __restrict__ fallback,
                       float4* __restrict__ out)
{
    __shared__ const float4* srcs[SAMPLES_PER_BLK];

    const int tid  = threadIdx.x;
    const int base = blockIdx.x * SAMPLES_PER_BLK;

    // Phase A: 32 threads resolve 32 independent source pointers.
    if (tid < SAMPLES_PER_BLK) {
        const int sample = base + tid;
        const int c   = __ldg(&tgt[sample]);
        const int cnt = __ldg(&counts[c]);
        const float4* p;
        if (cnt > 0) {
            const int idx = __ldg(&ridx[sample]) % cnt;
            p = bank + ((int64_t)c * CAPACITY + idx) * VEC_PER_ROW;
        } else {
            p = fallback + (int64_t)sample * VEC_PER_ROW;
        }
        srcs[tid] = p;
    }
    __syncthreads();

    // Phase B: copy 32 rows (32 KB). Each thread: 8 independent LDG.128
    // (as adjacent pairs) + 4 x 256-bit streaming stores.
    float4* const out_base = out + (int64_t)base * VEC_PER_ROW;

    float4 va[CHUNKS_PER_THR], vb[CHUNKS_PER_THR];
    #pragma unroll
    for (int k = 0; k < CHUNKS_PER_THR; ++k) {
        const int chunk = k * THREADS + tid;           // 0..1023
        const int s     = chunk >> 5;                  // sample within block
        const int lane  = chunk & (CHUNKS_PER_ROW - 1);// 32B chunk in row
        va[k] = __ldg(&srcs[s][lane * 2 + 0]);
        vb[k] = __ldg(&srcs[s][lane * 2 + 1]);
    }
    #pragma unroll
    for (int k = 0; k < CHUNKS_PER_THR; ++k) {
        const int chunk = k * THREADS + tid;
        st_cs_256(&out_base[chunk * 2], va[k], vb[k]);
    }
}

extern "C" void kernel_launch(void* const* d_in, const int* in_sizes, int n_in,
                              void* d_out, int out_size)
{
    const int*    tgt      = (const int*)   d_in[0];  // target_center_ids [B]
    const int*    ridx     = (const int*)   d_in[1];  // rand_idx          [B]
    const int*    counts   = (const int*)   d_in[2];  // counts            [NUM_CENTERS]
    const float4* bank     = (const float4*)d_in[3];  // bank [NC, CAP, D]
    const float4* fallback = (const float4*)d_in[4];  // fallback_noise [B, D]
    float4*       out      = (float4*)      d_out;    // [B, D] fp32

    const int grid = BATCH / SAMPLES_PER_BLK;  // 2048
    noise_bank_gather<<<grid, THREADS>>>(tgt, ridx, counts, bank, fallback, out);
}